// round 2
// baseline (speedup 1.0000x reference)
#include <cuda_runtime.h>
#include <cstdint>

#define WSZ   7
#define NTOK  49
#define NPAD  64
#define DIM   192
#define NHEAD 6
#define HDIM  32
#define QSCALE 0.17677669529663687f   // 1/sqrt(32)

// SMEM layout in floats:
//   sX   [0,      12288)  : X 64x192 (tf32 bits)   -- reused as sO (64x192) in attention/proj
//   sW   [12288,  18432)  : W staging 32x192       -- reused as sS (64x64 scores/probs)
//   sQKV [18432,  55296)  : QKV 64x576 (tf32 bits)
// total 55296 floats = 221184 bytes

__device__ __forceinline__ uint32_t f2tf(float f) {
    uint32_t u;
    asm volatile("cvt.rna.tf32.f32 %0, %1;" : "=r"(u) : "f"(f));
    return u;
}

__device__ __forceinline__ void mma_tf32(float& c0, float& c1, float& c2, float& c3,
                                         uint32_t a0, uint32_t a1, uint32_t a2, uint32_t a3,
                                         uint32_t b0, uint32_t b1) {
    asm volatile(
        "mma.sync.aligned.m16n8k8.row.col.f32.tf32.tf32.f32 "
        "{%0,%1,%2,%3},{%4,%5,%6,%7},{%8,%9},{%0,%1,%2,%3};"
        : "+f"(c0), "+f"(c1), "+f"(c2), "+f"(c3)
        : "r"(a0), "r"(a1), "r"(a2), "r"(a3), "r"(b0), "r"(b1));
}

extern "C" __global__ void __launch_bounds__(256, 1)
win_attn_fused(const float* __restrict__ x,
               const float* __restrict__ qkv_w,
               const float* __restrict__ qkv_b,
               const float* __restrict__ proj_w,
               const float* __restrict__ proj_b,
               const float* __restrict__ bias_table,
               const int*   __restrict__ rel_idx,
               float* __restrict__ out)
{
    extern __shared__ float smem[];
    float* sX   = smem;           // also sO
    float* sW   = smem + 12288;   // also sS
    float* sQKV = smem + 18432;

    const int b    = blockIdx.x;
    const int tid  = threadIdx.x;
    const int w    = tid >> 5;
    const int lane = tid & 31;
    const int lr   = lane >> 2;   // A/C frag row; B frag n-index
    const int lc   = lane & 3;    // A frag col; B frag k-index; C col-pair
    const int m0   = (w & 3) * 16;   // warp's M-tile base row
    const int nhf  = (w >> 2);       // warp's N-half (0/1) for 192-wide GEMMs

    const float* xb = x + (size_t)b * (NTOK * DIM);

    // ---------------- Phase 1: load X (pad to 64 rows), convert tf32 ----------------
    for (int i = tid; i < (NPAD * DIM) / 4; i += 256) {
        int row = i / 48;
        int c4  = (i % 48) * 4;
        float4 v = make_float4(0.f, 0.f, 0.f, 0.f);
        if (row < NTOK) v = *reinterpret_cast<const float4*>(xb + row * DIM + c4);
        uint4 t;
        t.x = f2tf(v.x); t.y = f2tf(v.y); t.z = f2tf(v.z); t.w = f2tf(v.w);
        *reinterpret_cast<uint4*>(sX + row * DIM + c4) = t;
    }

    // ---------------- Phase 2: QKV = X @ qkv_w + qkv_b  (64 x 576, K=192) ----------------
    // 3 N-blocks of 192 cols; per N-block, loop K in 6 chunks of 32 staged through sW.
    for (int nb = 0; nb < 3; ++nb) {
        float acc[12][4];
        #pragma unroll
        for (int t = 0; t < 12; ++t) {
            acc[t][0] = acc[t][1] = acc[t][2] = acc[t][3] = 0.f;
        }
        for (int kb = 0; kb < 6; ++kb) {
            __syncthreads();
            // stage qkv_w[kb*32 .. +32, nb*192 .. +192] -> sW (tf32)
            for (int i = tid; i < (32 * 192) / 4; i += 256) {
                int kk = i / 48;
                int c4 = (i % 48) * 4;
                float4 v = *reinterpret_cast<const float4*>(
                    qkv_w + (size_t)(kb * 32 + kk) * 576 + nb * 192 + c4);
                uint4 t;
                t.x = f2tf(v.x); t.y = f2tf(v.y); t.z = f2tf(v.z); t.w = f2tf(v.w);
                *reinterpret_cast<uint4*>(sW + kk * 192 + c4) = t;
            }
            __syncthreads();
            const uint32_t* uX = reinterpret_cast<const uint32_t*>(sX);
            const uint32_t* uW = reinterpret_cast<const uint32_t*>(sW);
            #pragma unroll
            for (int ks = 0; ks < 4; ++ks) {
                int k0 = kb * 32 + ks * 8;
                uint32_t a0 = uX[(m0 + lr)     * DIM + k0 + lc];
                uint32_t a1 = uX[(m0 + lr + 8) * DIM + k0 + lc];
                uint32_t a2 = uX[(m0 + lr)     * DIM + k0 + lc + 4];
                uint32_t a3 = uX[(m0 + lr + 8) * DIM + k0 + lc + 4];
                #pragma unroll
                for (int t = 0; t < 12; ++t) {
                    int n0 = nhf * 96 + t * 8;
                    uint32_t b0 = uW[(ks * 8 + lc)     * 192 + n0 + lr];
                    uint32_t b1 = uW[(ks * 8 + lc + 4) * 192 + n0 + lr];
                    mma_tf32(acc[t][0], acc[t][1], acc[t][2], acc[t][3],
                             a0, a1, a2, a3, b0, b1);
                }
            }
        }
        // epilogue: + qkv_b, store tf32 into sQKV
        #pragma unroll
        for (int t = 0; t < 12; ++t) {
            int cg  = nhf * 96 + t * 8 + lc * 2;
            int col = nb * 192 + cg;
            float bb0 = qkv_b[col];
            float bb1 = qkv_b[col + 1];
            sQKV[(m0 + lr)     * 576 + col]     = __uint_as_float(f2tf(acc[t][0] + bb0));
            sQKV[(m0 + lr)     * 576 + col + 1] = __uint_as_float(f2tf(acc[t][1] + bb1));
            sQKV[(m0 + lr + 8) * 576 + col]     = __uint_as_float(f2tf(acc[t][2] + bb0));
            sQKV[(m0 + lr + 8) * 576 + col + 1] = __uint_as_float(f2tf(acc[t][3] + bb1));
        }
    }

    // ---------------- Phase 3: per-head attention ----------------
    float* sS = sW;   // 64x64 scores / probs
    float* sO = sX;   // 64x192 attention output (X is dead after phase 2)

    for (int h = 0; h < NHEAD; ++h) {
        __syncthreads();   // sQKV ready (h=0); sS free of prior head's readers (h>0)

        // --- S = Q K^T * scale + bias, with column mask ---
        {
            const uint32_t* uQKV = reinterpret_cast<const uint32_t*>(sQKV);
            const int nq = w >> 2;   // 0/1 -> N-tiles [nq*4, nq*4+4)
            float acc[4][4];
            #pragma unroll
            for (int t = 0; t < 4; ++t) {
                acc[t][0] = acc[t][1] = acc[t][2] = acc[t][3] = 0.f;
            }
            #pragma unroll
            for (int kc = 0; kc < 4; ++kc) {
                int c0 = h * HDIM + kc * 8;
                uint32_t a0 = uQKV[(m0 + lr)     * 576 + c0 + lc];
                uint32_t a1 = uQKV[(m0 + lr + 8) * 576 + c0 + lc];
                uint32_t a2 = uQKV[(m0 + lr)     * 576 + c0 + lc + 4];
                uint32_t a3 = uQKV[(m0 + lr + 8) * 576 + c0 + lc + 4];
                #pragma unroll
                for (int t = 0; t < 4; ++t) {
                    int n0 = (nq * 4 + t) * 8;
                    // B[k][n] = K[n][k] ; K row n lives at sQKV[n*576 + 192 + h*32 + k]
                    uint32_t b0 = uQKV[(n0 + lr) * 576 + 192 + h * HDIM + kc * 8 + lc];
                    uint32_t b1 = uQKV[(n0 + lr) * 576 + 192 + h * HDIM + kc * 8 + lc + 4];
                    mma_tf32(acc[t][0], acc[t][1], acc[t][2], acc[t][3],
                             a0, a1, a2, a3, b0, b1);
                }
            }
            // epilogue: scale + relative-position bias + mask -> sS (fp32)
            #pragma unroll
            for (int t = 0; t < 4; ++t) {
                int cg = (nq * 4 + t) * 8 + lc * 2;
                #pragma unroll
                for (int half = 0; half < 2; ++half) {
                    int rg = m0 + lr + half * 8;
                    #pragma unroll
                    for (int cc = 0; cc < 2; ++cc) {
                        int cgl = cg + cc;
                        float v = acc[t][half * 2 + cc];
                        float s;
                        if (cgl < NTOK) {
                            s = v * QSCALE;
                            if (rg < NTOK)
                                s += bias_table[rel_idx[rg * NTOK + cgl] * NHEAD + h];
                        } else {
                            s = -1e30f;   // mask padded key columns
                        }
                        sS[rg * 64 + cgl] = s;
                    }
                }
            }
        }
        __syncthreads();

        // --- softmax over each of 64 rows (4 threads per row) ---
        {
            int row = tid >> 2;
            int q4  = tid & 3;
            float mx = -1e30f;
            for (int j = q4; j < 64; j += 4) mx = fmaxf(mx, sS[row * 64 + j]);
            mx = fmaxf(mx, __shfl_xor_sync(0xffffffffu, mx, 1));
            mx = fmaxf(mx, __shfl_xor_sync(0xffffffffu, mx, 2));
            float sum = 0.f;
            for (int j = q4; j < 64; j += 4) {
                float e = __expf(sS[row * 64 + j] - mx);
                sS[row * 64 + j] = e;
                sum += e;
            }
            sum += __shfl_xor_sync(0xffffffffu, sum, 1);
            sum += __shfl_xor_sync(0xffffffffu, sum, 2);
            float inv = 1.f / sum;
            for (int j = q4; j < 64; j += 4)
                sS[row * 64 + j] = __uint_as_float(f2tf(sS[row * 64 + j] * inv));
        }
        __syncthreads();

        // --- O_h = P @ V  (64 x 32, K=64) -> sO columns [h*32, h*32+32) ---
        {
            const uint32_t* uP = reinterpret_cast<const uint32_t*>(sS);
            const uint32_t* uV = reinterpret_cast<const uint32_t*>(sQKV);
            const int nq = w >> 2;   // 0/1 -> N-tiles {nq*2, nq*2+1}
            float acc[2][4];
            #pragma unroll
            for (int t = 0; t < 2; ++t) {
                acc[t][0] = acc[t][1] = acc[t][2] = acc[t][3] = 0.f;
            }
            #pragma unroll
            for (int kc = 0; kc < 8; ++kc) {
                uint32_t a0 = uP[(m0 + lr)     * 64 + kc * 8 + lc];
                uint32_t a1 = uP[(m0 + lr + 8) * 64 + kc * 8 + lc];
                uint32_t a2 = uP[(m0 + lr)     * 64 + kc * 8 + lc + 4];
                uint32_t a3 = uP[(m0 + lr + 8) * 64 + kc * 8 + lc + 4];
                #pragma unroll
                for (int t = 0; t < 2; ++t) {
                    int n0 = (nq * 2 + t) * 8;
                    // B[k][n] = V[k][n] ; V row k at sQKV[k*576 + 384 + h*32 + n]
                    uint32_t b0 = uV[(kc * 8 + lc)     * 576 + 384 + h * HDIM + n0 + lr];
                    uint32_t b1 = uV[(kc * 8 + lc + 4) * 576 + 384 + h * HDIM + n0 + lr];
                    mma_tf32(acc[t][0], acc[t][1], acc[t][2], acc[t][3],
                             a0, a1, a2, a3, b0, b1);
                }
            }
            #pragma unroll
            for (int t = 0; t < 2; ++t) {
                int cg = h * HDIM + (nq * 2 + t) * 8 + lc * 2;
                sO[(m0 + lr)     * 192 + cg]     = __uint_as_float(f2tf(acc[t][0]));
                sO[(m0 + lr)     * 192 + cg + 1] = __uint_as_float(f2tf(acc[t][1]));
                sO[(m0 + lr + 8) * 192 + cg]     = __uint_as_float(f2tf(acc[t][2]));
                sO[(m0 + lr + 8) * 192 + cg + 1] = __uint_as_float(f2tf(acc[t][3]));
            }
        }
    }

    // ---------------- Phase 4: Y = O @ proj_w + proj_b  (64 x 192, K=192) ----------------
    {
        float acc[12][4];
        #pragma unroll
        for (int t = 0; t < 12; ++t) {
            acc[t][0] = acc[t][1] = acc[t][2] = acc[t][3] = 0.f;
        }
        for (int kb = 0; kb < 6; ++kb) {
            __syncthreads();   // also covers sO writes / sS readers before first staging
            for (int i = tid; i < (32 * 192) / 4; i += 256) {
                int kk = i / 48;
                int c4 = (i % 48) * 4;
                float4 v = *reinterpret_cast<const float4*>(
                    proj_w + (size_t)(kb * 32 + kk) * 192 + c4);
                uint4 t;
                t.x = f2tf(v.x); t.y = f2tf(v.y); t.z = f2tf(v.z); t.w = f2tf(v.w);
                *reinterpret_cast<uint4*>(sW + kk * 192 + c4) = t;
            }
            __syncthreads();
            const uint32_t* uO = reinterpret_cast<const uint32_t*>(sX);
            const uint32_t* uW = reinterpret_cast<const uint32_t*>(sW);
            #pragma unroll
            for (int ks = 0; ks < 4; ++ks) {
                int k0 = kb * 32 + ks * 8;
                uint32_t a0 = uO[(m0 + lr)     * 192 + k0 + lc];
                uint32_t a1 = uO[(m0 + lr + 8) * 192 + k0 + lc];
                uint32_t a2 = uO[(m0 + lr)     * 192 + k0 + lc + 4];
                uint32_t a3 = uO[(m0 + lr + 8) * 192 + k0 + lc + 4];
                #pragma unroll
                for (int t = 0; t < 12; ++t) {
                    int n0 = nhf * 96 + t * 8;
                    uint32_t b0 = uW[(ks * 8 + lc)     * 192 + n0 + lr];
                    uint32_t b1 = uW[(ks * 8 + lc + 4) * 192 + n0 + lr];
                    mma_tf32(acc[t][0], acc[t][1], acc[t][2], acc[t][3],
                             a0, a1, a2, a3, b0, b1);
                }
            }
        }
        // epilogue: + proj_b, write valid rows to global
        float* ob = out + (size_t)b * (NTOK * DIM);
        #pragma unroll
        for (int t = 0; t < 12; ++t) {
            int cg = nhf * 96 + t * 8 + lc * 2;
            float bb0 = proj_b[cg];
            float bb1 = proj_b[cg + 1];
            int rg0 = m0 + lr;
            int rg1 = m0 + lr + 8;
            if (rg0 < NTOK) {
                ob[rg0 * DIM + cg]     = acc[t][0] + bb0;
                ob[rg0 * DIM + cg + 1] = acc[t][1] + bb1;
            }
            if (rg1 < NTOK) {
                ob[rg1 * DIM + cg]     = acc[t][2] + bb0;
                ob[rg1 * DIM + cg + 1] = acc[t][3] + bb1;
            }
        }
    }
}

extern "C" void kernel_launch(void* const* d_in, const int* in_sizes, int n_in,
                              void* d_out, int out_size)
{
    const float* x          = (const float*)d_in[0];
    const float* qkv_w      = (const float*)d_in[1];
    const float* qkv_b      = (const float*)d_in[2];
    const float* proj_w     = (const float*)d_in[3];
    const float* proj_b     = (const float*)d_in[4];
    const float* bias_table = (const float*)d_in[5];
    const int*   rel_idx    = (const int*)d_in[6];
    float* out = (float*)d_out;

    int nwin = in_sizes[0] / (NTOK * DIM);   // 4096

    const int smem_bytes = 55296 * 4;        // 221184 B dynamic smem
    cudaFuncSetAttribute(win_attn_fused,
                         cudaFuncAttributeMaxDynamicSharedMemorySize, smem_bytes);

    win_attn_fused<<<nwin, 256, smem_bytes>>>(x, qkv_w, qkv_b, proj_w, proj_b,
                                              bias_table, rel_idx, out);
}

// round 4
// speedup vs baseline: 1.7403x; 1.7403x over previous
#include <cuda_runtime.h>
#include <cstdint>

#define WSZ   7
#define NTOK  49
#define NPAD  64
#define DIM   192
#define NHEAD 6
#define HDIM  32
#define QSCALE 0.17677669529663687f   // 1/sqrt(32)

// Padded SMEM row strides (words), all == 4 (mod 32) -> conflict-free mma loads
#define XS 196   // sX / sO rows (192 data cols)
#define WS_ 196  // sW rows (192 data cols)
#define QS 580   // sQKV rows (576 data cols)
#define SS 68    // sS rows (64 data cols)

// SMEM layout (floats):
//   sX   [0,      12544)  : X 64xXS      -- reused as sO
//   sW   [12544,  18816)  : W 32xWS_     -- reused as sS (64xSS=4352 fits)
//   sQKV [18816,  55936)  : QKV 64xQS
// total 55936 floats = 223744 bytes

__device__ __forceinline__ uint32_t f2tf(float f) {
    uint32_t u;
    asm volatile("cvt.rna.tf32.f32 %0, %1;" : "=r"(u) : "f"(f));
    return u;
}

__device__ __forceinline__ void mma_tf32(float& c0, float& c1, float& c2, float& c3,
                                         uint32_t a0, uint32_t a1, uint32_t a2, uint32_t a3,
                                         uint32_t b0, uint32_t b1) {
    asm volatile(
        "mma.sync.aligned.m16n8k8.row.col.f32.tf32.tf32.f32 "
        "{%0,%1,%2,%3},{%4,%5,%6,%7},{%8,%9},{%0,%1,%2,%3};"
        : "+f"(c0), "+f"(c1), "+f"(c2), "+f"(c3)
        : "r"(a0), "r"(a1), "r"(a2), "r"(a3), "r"(b0), "r"(b1));
}

extern "C" __global__ void __launch_bounds__(256, 1)
win_attn_fused(const float* __restrict__ x,
               const float* __restrict__ qkv_w,
               const float* __restrict__ qkv_b,
               const float* __restrict__ proj_w,
               const float* __restrict__ proj_b,
               const float* __restrict__ bias_table,
               const int*   __restrict__ rel_idx,
               float* __restrict__ out)
{
    extern __shared__ float smem[];
    float* sX   = smem;           // also sO
    float* sW   = smem + 12544;   // also sS
    float* sQKV = smem + 18816;

    const int b    = blockIdx.x;
    const int tid  = threadIdx.x;
    const int w    = tid >> 5;
    const int lane = tid & 31;
    const int lr   = lane >> 2;   // A/C frag row; B frag n-index
    const int lc   = lane & 3;    // A frag col; B frag k-index; C col-pair
    const int m0   = (w & 3) * 16;   // warp's M-tile base row
    const int nhf  = (w >> 2);       // warp's N-half (0/1) for 192-wide GEMMs

    const float* xb = x + (size_t)b * (NTOK * DIM);

    // ---------------- Phase 1: load X (pad to 64 rows), convert tf32 ----------------
    for (int i = tid; i < (NPAD * DIM) / 4; i += 256) {
        int row = i / 48;
        int c4  = (i % 48) * 4;
        float4 v = make_float4(0.f, 0.f, 0.f, 0.f);
        if (row < NTOK) v = *reinterpret_cast<const float4*>(xb + row * DIM + c4);
        uint4 t;
        t.x = f2tf(v.x); t.y = f2tf(v.y); t.z = f2tf(v.z); t.w = f2tf(v.w);
        *reinterpret_cast<uint4*>(sX + row * XS + c4) = t;
    }

    // ---------------- Phase 2: QKV = X @ qkv_w + qkv_b  (64 x 576, K=192) ----------------
    for (int nb = 0; nb < 3; ++nb) {
        float acc[12][4];
        #pragma unroll
        for (int t = 0; t < 12; ++t) {
            acc[t][0] = acc[t][1] = acc[t][2] = acc[t][3] = 0.f;
        }
        for (int kb = 0; kb < 6; ++kb) {
            __syncthreads();
            // stage qkv_w[kb*32 .. +32, nb*192 .. +192] -> sW (tf32)
            for (int i = tid; i < (32 * 192) / 4; i += 256) {
                int kk = i / 48;
                int c4 = (i % 48) * 4;
                float4 v = *reinterpret_cast<const float4*>(
                    qkv_w + (size_t)(kb * 32 + kk) * 576 + nb * 192 + c4);
                uint4 t;
                t.x = f2tf(v.x); t.y = f2tf(v.y); t.z = f2tf(v.z); t.w = f2tf(v.w);
                *reinterpret_cast<uint4*>(sW + kk * WS_ + c4) = t;
            }
            __syncthreads();
            const uint32_t* uX = reinterpret_cast<const uint32_t*>(sX);
            const uint32_t* uW = reinterpret_cast<const uint32_t*>(sW);
            #pragma unroll
            for (int ks = 0; ks < 4; ++ks) {
                int k0 = kb * 32 + ks * 8;
                uint32_t a0 = uX[(m0 + lr)     * XS + k0 + lc];
                uint32_t a1 = uX[(m0 + lr + 8) * XS + k0 + lc];
                uint32_t a2 = uX[(m0 + lr)     * XS + k0 + lc + 4];
                uint32_t a3 = uX[(m0 + lr + 8) * XS + k0 + lc + 4];
                #pragma unroll
                for (int t = 0; t < 12; ++t) {
                    int n0 = nhf * 96 + t * 8;
                    uint32_t b0 = uW[(ks * 8 + lc)     * WS_ + n0 + lr];
                    uint32_t b1 = uW[(ks * 8 + lc + 4) * WS_ + n0 + lr];
                    mma_tf32(acc[t][0], acc[t][1], acc[t][2], acc[t][3],
                             a0, a1, a2, a3, b0, b1);
                }
            }
        }
        // epilogue: + qkv_b, store tf32 into sQKV
        #pragma unroll
        for (int t = 0; t < 12; ++t) {
            int cg  = nhf * 96 + t * 8 + lc * 2;
            int col = nb * 192 + cg;
            float bb0 = qkv_b[col];
            float bb1 = qkv_b[col + 1];
            sQKV[(m0 + lr)     * QS + col]     = __uint_as_float(f2tf(acc[t][0] + bb0));
            sQKV[(m0 + lr)     * QS + col + 1] = __uint_as_float(f2tf(acc[t][1] + bb1));
            sQKV[(m0 + lr + 8) * QS + col]     = __uint_as_float(f2tf(acc[t][2] + bb0));
            sQKV[(m0 + lr + 8) * QS + col + 1] = __uint_as_float(f2tf(acc[t][3] + bb1));
        }
    }

    // ---------------- Phase 3: per-head attention ----------------
    float* sS = sW;   // 64xSS scores / probs
    float* sO = sX;   // 64xXS attention output (X dead after phase 2)

    for (int h = 0; h < NHEAD; ++h) {
        __syncthreads();   // sQKV ready (h=0); sS free of prior readers (h>0)

        // --- S = Q K^T * scale + bias, with column mask ---
        {
            const uint32_t* uQKV = reinterpret_cast<const uint32_t*>(sQKV);
            const int nq = w >> 2;   // 0/1 -> N-tiles [nq*4, nq*4+4)
            float acc[4][4];
            #pragma unroll
            for (int t = 0; t < 4; ++t) {
                acc[t][0] = acc[t][1] = acc[t][2] = acc[t][3] = 0.f;
            }
            #pragma unroll
            for (int kc = 0; kc < 4; ++kc) {
                int c0 = h * HDIM + kc * 8;
                uint32_t a0 = uQKV[(m0 + lr)     * QS + c0 + lc];
                uint32_t a1 = uQKV[(m0 + lr + 8) * QS + c0 + lc];
                uint32_t a2 = uQKV[(m0 + lr)     * QS + c0 + lc + 4];
                uint32_t a3 = uQKV[(m0 + lr + 8) * QS + c0 + lc + 4];
                #pragma unroll
                for (int t = 0; t < 4; ++t) {
                    int n0 = (nq * 4 + t) * 8;
                    uint32_t b0 = uQKV[(n0 + lr) * QS + 192 + h * HDIM + kc * 8 + lc];
                    uint32_t b1 = uQKV[(n0 + lr) * QS + 192 + h * HDIM + kc * 8 + lc + 4];
                    mma_tf32(acc[t][0], acc[t][1], acc[t][2], acc[t][3],
                             a0, a1, a2, a3, b0, b1);
                }
            }
            // epilogue: scale + relative-position bias + mask -> sS (fp32)
            #pragma unroll
            for (int t = 0; t < 4; ++t) {
                int cg = (nq * 4 + t) * 8 + lc * 2;
                #pragma unroll
                for (int half = 0; half < 2; ++half) {
                    int rg = m0 + lr + half * 8;
                    #pragma unroll
                    for (int cc = 0; cc < 2; ++cc) {
                        int cgl = cg + cc;
                        float v = acc[t][half * 2 + cc];
                        float s;
                        if (cgl < NTOK) {
                            s = v * QSCALE;
                            if (rg < NTOK)
                                s += bias_table[rel_idx[rg * NTOK + cgl] * NHEAD + h];
                        } else {
                            s = -1e30f;   // mask padded key columns
                        }
                        sS[rg * SS + cgl] = s;
                    }
                }
            }
        }
        __syncthreads();

        // --- softmax over each of 64 rows (4 threads per row) ---
        {
            int row = tid >> 2;
            int q4  = tid & 3;
            float mx = -1e30f;
            for (int j = q4; j < 64; j += 4) mx = fmaxf(mx, sS[row * SS + j]);
            mx = fmaxf(mx, __shfl_xor_sync(0xffffffffu, mx, 1));
            mx = fmaxf(mx, __shfl_xor_sync(0xffffffffu, mx, 2));
            float sum = 0.f;
            for (int j = q4; j < 64; j += 4) {
                float e = __expf(sS[row * SS + j] - mx);
                sS[row * SS + j] = e;
                sum += e;
            }
            sum += __shfl_xor_sync(0xffffffffu, sum, 1);
            sum += __shfl_xor_sync(0xffffffffu, sum, 2);
            float inv = 1.f / sum;
            for (int j = q4; j < 64; j += 4)
                sS[row * SS + j] = __uint_as_float(f2tf(sS[row * SS + j] * inv));
        }
        __syncthreads();

        // --- O_h = P @ V  (64 x 32, K=64) -> sO columns [h*32, h*32+32) ---
        {
            const uint32_t* uP = reinterpret_cast<const uint32_t*>(sS);
            const uint32_t* uV = reinterpret_cast<const uint32_t*>(sQKV);
            const int nq = w >> 2;
            float acc[2][4];
            #pragma unroll
            for (int t = 0; t < 2; ++t) {
                acc[t][0] = acc[t][1] = acc[t][2] = acc[t][3] = 0.f;
            }
            #pragma unroll
            for (int kc = 0; kc < 8; ++kc) {
                uint32_t a0 = uP[(m0 + lr)     * SS + kc * 8 + lc];
                uint32_t a1 = uP[(m0 + lr + 8) * SS + kc * 8 + lc];
                uint32_t a2 = uP[(m0 + lr)     * SS + kc * 8 + lc + 4];
                uint32_t a3 = uP[(m0 + lr + 8) * SS + kc * 8 + lc + 4];
                #pragma unroll
                for (int t = 0; t < 2; ++t) {
                    int n0 = (nq * 2 + t) * 8;
                    uint32_t b0 = uV[(kc * 8 + lc)     * QS + 384 + h * HDIM + n0 + lr];
                    uint32_t b1 = uV[(kc * 8 + lc + 4) * QS + 384 + h * HDIM + n0 + lr];
                    mma_tf32(acc[t][0], acc[t][1], acc[t][2], acc[t][3],
                             a0, a1, a2, a3, b0, b1);
                }
            }
            #pragma unroll
            for (int t = 0; t < 2; ++t) {
                int cg = h * HDIM + (nq * 2 + t) * 8 + lc * 2;
                sO[(m0 + lr)     * XS + cg]     = __uint_as_float(f2tf(acc[t][0]));
                sO[(m0 + lr)     * XS + cg + 1] = __uint_as_float(f2tf(acc[t][1]));
                sO[(m0 + lr + 8) * XS + cg]     = __uint_as_float(f2tf(acc[t][2]));
                sO[(m0 + lr + 8) * XS + cg + 1] = __uint_as_float(f2tf(acc[t][3]));
            }
        }
    }

    // ---------------- Phase 4: Y = O @ proj_w + proj_b  (64 x 192, K=192) ----------------
    {
        float acc[12][4];
        #pragma unroll
        for (int t = 0; t < 12; ++t) {
            acc[t][0] = acc[t][1] = acc[t][2] = acc[t][3] = 0.f;
        }
        for (int kb = 0; kb < 6; ++kb) {
            __syncthreads();
            for (int i = tid; i < (32 * 192) / 4; i += 256) {
                int kk = i / 48;
                int c4 = (i % 48) * 4;
                float4 v = *reinterpret_cast<const float4*>(
                    proj_w + (size_t)(kb * 32 + kk) * 192 + c4);
                uint4 t;
                t.x = f2tf(v.x); t.y = f2tf(v.y); t.z = f2tf(v.z); t.w = f2tf(v.w);
                *reinterpret_cast<uint4*>(sW + kk * WS_ + c4) = t;
            }
            __syncthreads();
            const uint32_t* uO = reinterpret_cast<const uint32_t*>(sX);
            const uint32_t* uW = reinterpret_cast<const uint32_t*>(sW);
            #pragma unroll
            for (int ks = 0; ks < 4; ++ks) {
                int k0 = kb * 32 + ks * 8;
                uint32_t a0 = uO[(m0 + lr)     * XS + k0 + lc];
                uint32_t a1 = uO[(m0 + lr + 8) * XS + k0 + lc];
                uint32_t a2 = uO[(m0 + lr)     * XS + k0 + lc + 4];
                uint32_t a3 = uO[(m0 + lr + 8) * XS + k0 + lc + 4];
                #pragma unroll
                for (int t = 0; t < 12; ++t) {
                    int n0 = nhf * 96 + t * 8;
                    uint32_t b0 = uW[(ks * 8 + lc)     * WS_ + n0 + lr];
                    uint32_t b1 = uW[(ks * 8 + lc + 4) * WS_ + n0 + lr];
                    mma_tf32(acc[t][0], acc[t][1], acc[t][2], acc[t][3],
                             a0, a1, a2, a3, b0, b1);
                }
            }
        }
        // epilogue: + proj_b, write valid rows to global
        float* ob = out + (size_t)b * (NTOK * DIM);
        #pragma unroll
        for (int t = 0; t < 12; ++t) {
            int cg = nhf * 96 + t * 8 + lc * 2;
            float bb0 = proj_b[cg];
            float bb1 = proj_b[cg + 1];
            int rg0 = m0 + lr;
            int rg1 = m0 + lr + 8;
            if (rg0 < NTOK) {
                ob[rg0 * DIM + cg]     = acc[t][0] + bb0;
                ob[rg0 * DIM + cg + 1] = acc[t][1] + bb1;
            }
            if (rg1 < NTOK) {
                ob[rg1 * DIM + cg]     = acc[t][2] + bb0;
                ob[rg1 * DIM + cg + 1] = acc[t][3] + bb1;
            }
        }
    }
}

extern "C" void kernel_launch(void* const* d_in, const int* in_sizes, int n_in,
                              void* d_out, int out_size)
{
    const float* x          = (const float*)d_in[0];
    const float* qkv_w      = (const float*)d_in[1];
    const float* qkv_b      = (const float*)d_in[2];
    const float* proj_w     = (const float*)d_in[3];
    const float* proj_b     = (const float*)d_in[4];
    const float* bias_table = (const float*)d_in[5];
    const int*   rel_idx    = (const int*)d_in[6];
    float* out = (float*)d_out;

    int nwin = in_sizes[0] / (NTOK * DIM);   // 4096

    const int smem_bytes = 55936 * 4;        // 223744 B dynamic smem
    cudaFuncSetAttribute(win_attn_fused,
                         cudaFuncAttributeMaxDynamicSharedMemorySize, smem_bytes);

    win_attn_fused<<<nwin, 256, smem_bytes>>>(x, qkv_w, qkv_b, proj_w, proj_b,
                                              bias_table, rel_idx, out);
}

// round 8
// speedup vs baseline: 3.4664x; 1.9918x over previous
#include <cuda_runtime.h>
#include <cstdint>

#define NTOK  49
#define DIM   192
#define NHEAD 6
#define HDIM  32
#define QSCALE 0.17677669529663687f   // 1/sqrt(32)

#define MTOT  200704                   // 4096*49, divisible by 128

// device-global scratch (allocation-free workaround)
__device__ float g_qkv[(size_t)MTOT * 576];   // 462 MB
__device__ float g_o  [(size_t)MTOT * 192];   // 154 MB

__device__ __forceinline__ uint32_t f2tf(float f) {
    uint32_t u;
    asm volatile("cvt.rna.tf32.f32 %0, %1;" : "=r"(u) : "f"(f));
    return u;
}

__device__ __forceinline__ void mma_tf32(float* c,
                                         uint32_t a0, uint32_t a1, uint32_t a2, uint32_t a3,
                                         uint32_t b0, uint32_t b1) {
    asm volatile(
        "mma.sync.aligned.m16n8k8.row.col.f32.tf32.tf32.f32 "
        "{%0,%1,%2,%3},{%4,%5,%6,%7},{%8,%9},{%0,%1,%2,%3};"
        : "+f"(c[0]), "+f"(c[1]), "+f"(c[2]), "+f"(c[3])
        : "r"(a0), "r"(a1), "r"(a2), "r"(a3), "r"(b0), "r"(b1));
}

// ---------------------------------------------------------------------------
// GEMM: C[M, NT] = A[M,192] @ W[192, NT] + bias, tf32 mma, double-buffered.
// Block tile 128x96, K-chunk 32, warp tile 32x48 (8 warps: 4M x 2N).
// smem: sA[2][128*36] + sB[2][32*100] = 62464 B
// ---------------------------------------------------------------------------
template<int NT>
__device__ __forceinline__ void gemm_body(const float* __restrict__ A,
                                          const float* __restrict__ W,
                                          const float* __restrict__ bias,
                                          float* __restrict__ C)
{
    extern __shared__ float sm[];
    float* sA = sm;                    // [2][128*36]
    float* sB = sm + 2 * 128 * 36;     // [2][32*100]

    const int tid  = threadIdx.x;
    const int w    = tid >> 5;
    const int lane = tid & 31;
    const int lr   = lane >> 2;
    const int lc   = lane & 3;
    const int wm   = (w & 3) * 32;     // warp M offset in block
    const int wn   = (w >> 2) * 48;    // warp N offset in block
    const size_t bm = (size_t)blockIdx.x * 128;
    const int    bn = blockIdx.y * 96;

    float4 pa[4];
    float4 pb[3];

    auto ldg = [&](int kb) {
        #pragma unroll
        for (int i = 0; i < 4; ++i) {
            int idx = tid + i * 256;           // 0..1023 over 128x8 float4
            int r   = idx >> 3;
            int c4  = (idx & 7) * 4;
            pa[i] = *reinterpret_cast<const float4*>(A + (bm + r) * 192 + kb * 32 + c4);
        }
        #pragma unroll
        for (int i = 0; i < 3; ++i) {
            int idx = tid + i * 256;           // 0..767 over 32x24 float4
            int r   = idx / 24;
            int c4  = (idx % 24) * 4;
            pb[i] = *reinterpret_cast<const float4*>(W + (size_t)(kb * 32 + r) * NT + bn + c4);
        }
    };
    auto sts = [&](int buf) {
        float* dA = sA + buf * (128 * 36);
        float* dB = sB + buf * (32 * 100);
        #pragma unroll
        for (int i = 0; i < 4; ++i) {
            int idx = tid + i * 256;
            int r   = idx >> 3;
            int c4  = (idx & 7) * 4;
            uint4 t;
            t.x = f2tf(pa[i].x); t.y = f2tf(pa[i].y);
            t.z = f2tf(pa[i].z); t.w = f2tf(pa[i].w);
            *reinterpret_cast<uint4*>(dA + r * 36 + c4) = t;
        }
        #pragma unroll
        for (int i = 0; i < 3; ++i) {
            int idx = tid + i * 256;
            int r   = idx / 24;
            int c4  = (idx % 24) * 4;
            uint4 t;
            t.x = f2tf(pb[i].x); t.y = f2tf(pb[i].y);
            t.z = f2tf(pb[i].z); t.w = f2tf(pb[i].w);
            *reinterpret_cast<uint4*>(dB + r * 100 + c4) = t;
        }
    };

    float acc[2][6][4];
    #pragma unroll
    for (int mt = 0; mt < 2; ++mt)
        #pragma unroll
        for (int nt = 0; nt < 6; ++nt)
            acc[mt][nt][0] = acc[mt][nt][1] = acc[mt][nt][2] = acc[mt][nt][3] = 0.f;

    ldg(0);
    sts(0);
    __syncthreads();

    #pragma unroll
    for (int kb = 0; kb < 6; ++kb) {
        if (kb < 5) ldg(kb + 1);
        const uint32_t* uA = reinterpret_cast<const uint32_t*>(sA + (kb & 1) * (128 * 36));
        const uint32_t* uB = reinterpret_cast<const uint32_t*>(sB + (kb & 1) * (32 * 100));
        #pragma unroll
        for (int ks = 0; ks < 4; ++ks) {
            const int k0 = ks * 8;
            uint32_t a[2][4];
            #pragma unroll
            for (int mt = 0; mt < 2; ++mt) {
                int rb = wm + mt * 16;
                a[mt][0] = uA[(rb + lr)     * 36 + k0 + lc];
                a[mt][1] = uA[(rb + lr + 8) * 36 + k0 + lc];
                a[mt][2] = uA[(rb + lr)     * 36 + k0 + lc + 4];
                a[mt][3] = uA[(rb + lr + 8) * 36 + k0 + lc + 4];
            }
            #pragma unroll
            for (int nt = 0; nt < 6; ++nt) {
                int n0 = wn + nt * 8;
                uint32_t b0 = uB[(k0 + lc)     * 100 + n0 + lr];
                uint32_t b1 = uB[(k0 + lc + 4) * 100 + n0 + lr];
                mma_tf32(acc[0][nt], a[0][0], a[0][1], a[0][2], a[0][3], b0, b1);
                mma_tf32(acc[1][nt], a[1][0], a[1][1], a[1][2], a[1][3], b0, b1);
            }
        }
        if (kb < 5) {
            sts((kb + 1) & 1);
            __syncthreads();
        }
    }

    // epilogue: + bias, fp32 store (all rows/cols in bounds by construction)
    #pragma unroll
    for (int mt = 0; mt < 2; ++mt) {
        size_t r0 = bm + wm + mt * 16 + lr;
        size_t r1 = r0 + 8;
        #pragma unroll
        for (int nt = 0; nt < 6; ++nt) {
            int c = bn + wn + nt * 8 + lc * 2;
            float bb0 = bias[c];
            float bb1 = bias[c + 1];
            C[r0 * NT + c]     = acc[mt][nt][0] + bb0;
            C[r0 * NT + c + 1] = acc[mt][nt][1] + bb1;
            C[r1 * NT + c]     = acc[mt][nt][2] + bb0;
            C[r1 * NT + c + 1] = acc[mt][nt][3] + bb1;
        }
    }
}

extern "C" __global__ void __launch_bounds__(256, 2)
k1_qkv_gemm(const float* __restrict__ x,
            const float* __restrict__ qkv_w,
            const float* __restrict__ qkv_b)
{
    gemm_body<576>(x, qkv_w, qkv_b, g_qkv);
}

extern "C" __global__ void __launch_bounds__(256, 2)
k3_proj_gemm(const float* __restrict__ proj_w,
             const float* __restrict__ proj_b,
             float* __restrict__ out)
{
    gemm_body<192>(g_o, proj_w, proj_b, out);
}

// ---------------------------------------------------------------------------
// K2: attention. One CTA per (window, head). 128 threads (4 warps).
// smem: sQ/sK/sV 64x36 each + sS 64x68 = 45056 B.
// ---------------------------------------------------------------------------
extern "C" __global__ void __launch_bounds__(128)
k2_attention(const float* __restrict__ bias_table,
             const int*   __restrict__ rel_idx)
{
    extern __shared__ float sm[];
    float* sQ = sm;                //  64*36
    float* sK = sm + 64 * 36;
    float* sV = sm + 2 * 64 * 36;
    float* sS = sm + 3 * 64 * 36;  //  64*68

    const int win  = blockIdx.x;
    const int h    = blockIdx.y;
    const int tid  = threadIdx.x;
    const int w    = tid >> 5;
    const int lane = tid & 31;
    const int lr   = lane >> 2;
    const int lc   = lane & 3;
    const int m0   = w * 16;

    const size_t base = (size_t)win * NTOK * 576;

    // load Q (pre-scaled), K, V for this head; pad rows 49..63 with zeros
    for (int i = tid; i < 512; i += 128) {
        int r  = i >> 3;
        int c4 = (i & 7) * 4;
        float4 q = make_float4(0.f, 0.f, 0.f, 0.f);
        float4 k = q, v = q;
        if (r < NTOK) {
            const float* row = g_qkv + base + (size_t)r * 576 + h * HDIM + c4;
            q = *reinterpret_cast<const float4*>(row);
            k = *reinterpret_cast<const float4*>(row + 192);
            v = *reinterpret_cast<const float4*>(row + 384);
        }
        uint4 tq, tk, tv;
        tq.x = f2tf(q.x * QSCALE); tq.y = f2tf(q.y * QSCALE);
        tq.z = f2tf(q.z * QSCALE); tq.w = f2tf(q.w * QSCALE);
        tk.x = f2tf(k.x); tk.y = f2tf(k.y); tk.z = f2tf(k.z); tk.w = f2tf(k.w);
        tv.x = f2tf(v.x); tv.y = f2tf(v.y); tv.z = f2tf(v.z); tv.w = f2tf(v.w);
        *reinterpret_cast<uint4*>(sQ + r * 36 + c4) = tq;
        *reinterpret_cast<uint4*>(sK + r * 36 + c4) = tk;
        *reinterpret_cast<uint4*>(sV + r * 36 + c4) = tv;
    }
    __syncthreads();

    // --- S = Qs K^T + bias : warp w does rows [m0, m0+16), all 64 cols ---
    {
        const uint32_t* uQ = reinterpret_cast<const uint32_t*>(sQ);
        const uint32_t* uK = reinterpret_cast<const uint32_t*>(sK);
        float acc[8][4];
        #pragma unroll
        for (int nt = 0; nt < 8; ++nt)
            acc[nt][0] = acc[nt][1] = acc[nt][2] = acc[nt][3] = 0.f;
        #pragma unroll
        for (int kc = 0; kc < 4; ++kc) {
            uint32_t a0 = uQ[(m0 + lr)     * 36 + kc * 8 + lc];
            uint32_t a1 = uQ[(m0 + lr + 8) * 36 + kc * 8 + lc];
            uint32_t a2 = uQ[(m0 + lr)     * 36 + kc * 8 + lc + 4];
            uint32_t a3 = uQ[(m0 + lr + 8) * 36 + kc * 8 + lc + 4];
            #pragma unroll
            for (int nt = 0; nt < 8; ++nt) {
                uint32_t b0 = uK[(nt * 8 + lr) * 36 + kc * 8 + lc];
                uint32_t b1 = uK[(nt * 8 + lr) * 36 + kc * 8 + lc + 4];
                mma_tf32(acc[nt], a0, a1, a2, a3, b0, b1);
            }
        }
        #pragma unroll
        for (int nt = 0; nt < 8; ++nt) {
            #pragma unroll
            for (int half = 0; half < 2; ++half) {
                int rg = m0 + lr + half * 8;
                #pragma unroll
                for (int cc = 0; cc < 2; ++cc) {
                    int cgl = nt * 8 + lc * 2 + cc;
                    float s;
                    if (cgl < NTOK) {
                        s = acc[nt][half * 2 + cc];
                        if (rg < NTOK)
                            s += bias_table[rel_idx[rg * NTOK + cgl] * NHEAD + h];
                    } else {
                        s = -1e30f;
                    }
                    sS[rg * 68 + cgl] = s;
                }
            }
        }
    }
    __syncthreads();

    // --- softmax: 2 threads per row ---
    {
        int row  = tid >> 1;
        int half = tid & 1;
        float* rp = sS + row * 68 + half * 32;
        float mx = -1e30f;
        #pragma unroll
        for (int j = 0; j < 32; ++j) mx = fmaxf(mx, rp[j]);
        mx = fmaxf(mx, __shfl_xor_sync(0xffffffffu, mx, 1));
        float sum = 0.f;
        #pragma unroll
        for (int j = 0; j < 32; ++j) {
            float e = __expf(rp[j] - mx);
            rp[j] = e;
            sum += e;
        }
        sum += __shfl_xor_sync(0xffffffffu, sum, 1);
        float inv = 1.f / sum;
        #pragma unroll
        for (int j = 0; j < 32; ++j)
            rp[j] = __uint_as_float(f2tf(rp[j] * inv));
    }
    __syncthreads();

    // --- O = P V : warp w rows [m0, m0+16), 32 cols ---
    {
        const uint32_t* uP = reinterpret_cast<const uint32_t*>(sS);
        const uint32_t* uV = reinterpret_cast<const uint32_t*>(sV);
        float acc[4][4];
        #pragma unroll
        for (int nt = 0; nt < 4; ++nt)
            acc[nt][0] = acc[nt][1] = acc[nt][2] = acc[nt][3] = 0.f;
        #pragma unroll
        for (int kc = 0; kc < 8; ++kc) {
            uint32_t a0 = uP[(m0 + lr)     * 68 + kc * 8 + lc];
            uint32_t a1 = uP[(m0 + lr + 8) * 68 + kc * 8 + lc];
            uint32_t a2 = uP[(m0 + lr)     * 68 + kc * 8 + lc + 4];
            uint32_t a3 = uP[(m0 + lr + 8) * 68 + kc * 8 + lc + 4];
            #pragma unroll
            for (int nt = 0; nt < 4; ++nt) {
                uint32_t b0 = uV[(kc * 8 + lc)     * 36 + nt * 8 + lr];
                uint32_t b1 = uV[(kc * 8 + lc + 4) * 36 + nt * 8 + lr];
                mma_tf32(acc[nt], a0, a1, a2, a3, b0, b1);
            }
        }
        int rg0 = m0 + lr;
        int rg1 = rg0 + 8;
        #pragma unroll
        for (int nt = 0; nt < 4; ++nt) {
            int cg = nt * 8 + lc * 2;
            if (rg0 < NTOK) {
                float* o = g_o + ((size_t)win * NTOK + rg0) * 192 + h * HDIM + cg;
                o[0] = acc[nt][0];
                o[1] = acc[nt][1];
            }
            if (rg1 < NTOK) {
                float* o = g_o + ((size_t)win * NTOK + rg1) * 192 + h * HDIM + cg;
                o[0] = acc[nt][2];
                o[1] = acc[nt][3];
            }
        }
    }
}

// ---------------------------------------------------------------------------

extern "C" void kernel_launch(void* const* d_in, const int* in_sizes, int n_in,
                              void* d_out, int out_size)
{
    const float* x          = (const float*)d_in[0];
    const float* qkv_w      = (const float*)d_in[1];
    const float* qkv_b      = (const float*)d_in[2];
    const float* proj_w     = (const float*)d_in[3];
    const float* proj_b     = (const float*)d_in[4];
    const float* bias_table = (const float*)d_in[5];
    const int*   rel_idx    = (const int*)d_in[6];
    float* out = (float*)d_out;

    const int M      = in_sizes[0] / DIM;       // 200704
    const int mblks  = M / 128;                 // 1568
    const int nwin   = M / NTOK;                // 4096

    const int gemm_smem = (2 * 128 * 36 + 2 * 32 * 100) * 4;   // 62464
    const int attn_smem = (3 * 64 * 36 + 64 * 68) * 4;         // 45056

    cudaFuncSetAttribute(k1_qkv_gemm,
                         cudaFuncAttributeMaxDynamicSharedMemorySize, gemm_smem);
    cudaFuncSetAttribute(k3_proj_gemm,
                         cudaFuncAttributeMaxDynamicSharedMemorySize, gemm_smem);
    cudaFuncSetAttribute(k2_attention,
                         cudaFuncAttributeMaxDynamicSharedMemorySize, attn_smem);

    dim3 g1(mblks, 6);     // N=576 -> 6 blocks of 96
    k1_qkv_gemm<<<g1, 256, gemm_smem>>>(x, qkv_w, qkv_b);

    dim3 g2(nwin, NHEAD);
    k2_attention<<<g2, 128, attn_smem>>>(bias_table, rel_idx);

    dim3 g3(mblks, 2);     // N=192 -> 2 blocks of 96
    k3_proj_gemm<<<g3, 256, gemm_smem>>>(proj_w, proj_b, out);
}

// round 10
// speedup vs baseline: 3.7032x; 1.0683x over previous
#include <cuda_runtime.h>
#include <cstdint>

#define NTOK  49
#define DIM   192
#define NHEAD 6
#define HDIM  32
#define QSCALE 0.17677669529663687f   // 1/sqrt(32)
#define MTOT  200704                   // 4096*49

// device-global scratch (allocation-free workaround)
__device__ float g_qkv [(size_t)MTOT * 576];        // 462 MB
__device__ float g_o   [(size_t)MTOT * 192];        // 154 MB
__device__ float g_bias[NHEAD * NTOK * NTOK];       // 57.6 kB, precomputed bias

__device__ __forceinline__ uint32_t f2tf(float f) {
    uint32_t u;
    asm volatile("cvt.rna.tf32.f32 %0, %1;" : "=r"(u) : "f"(f));
    return u;
}

__device__ __forceinline__ void mma_tf32(float* c,
                                         uint32_t a0, uint32_t a1, uint32_t a2, uint32_t a3,
                                         uint32_t b0, uint32_t b1) {
    asm volatile(
        "mma.sync.aligned.m16n8k8.row.col.f32.tf32.tf32.f32 "
        "{%0,%1,%2,%3},{%4,%5,%6,%7},{%8,%9},{%0,%1,%2,%3};"
        : "+f"(c[0]), "+f"(c[1]), "+f"(c[2]), "+f"(c[3])
        : "r"(a0), "r"(a1), "r"(a2), "r"(a3), "r"(b0), "r"(b1));
}

// ---------------------------------------------------------------------------
// k0: precompute bias matrix g_bias[h][m][n] = bias_table[rel_idx[m*49+n]*6+h]
// ---------------------------------------------------------------------------
extern "C" __global__ void k0_bias(const float* __restrict__ bias_table,
                                   const int*   __restrict__ rel_idx)
{
    int h = blockIdx.x;
    for (int i = threadIdx.x; i < NTOK * NTOK; i += 256)
        g_bias[h * (NTOK * NTOK) + i] = bias_table[rel_idx[i] * NHEAD + h];
}

// ---------------------------------------------------------------------------
// GEMM: C[M,NT] = A[M,192] @ W[192,NT] + bias.
// grid (NT/96, M/128), block 128 (4 warps, 2M x 2N of 64x48 warp tiles).
// K-chunk 16, double buffered.
// SMEM: sA 2 x [128 x 20] (stride 20 == 4 mod 32: A-pattern conflict-free)
//       sB 2 x [16 x 104] (stride 104 == 8 mod 32: B-pattern conflict-free)
// Grid.x fastest => the NT/96 CTAs sharing one A-slab run adjacently -> A
// re-reads hit L2.
// ---------------------------------------------------------------------------
#define SA_STR 20
#define SB_STR 104
#define SA_BUF (128 * SA_STR)
#define SB_BUF (16 * SB_STR)
#define GEMM_SMEM ((2 * SA_BUF + 2 * SB_BUF) * 4)   // 33792 B

template<int NT>
__device__ __forceinline__ void gemm_body(const float* __restrict__ A,
                                          const float* __restrict__ W,
                                          const float* __restrict__ bias,
                                          float* __restrict__ C)
{
    extern __shared__ float sm[];
    float* sA = sm;
    float* sB = sm + 2 * SA_BUF;

    const int tid  = threadIdx.x;
    const int w    = tid >> 5;
    const int lane = tid & 31;
    const int lr   = lane >> 2;
    const int lc   = lane & 3;
    const int wm   = (w & 1) * 64;      // warp M offset
    const int wn   = (w >> 1) * 48;     // warp N offset
    const size_t bm = (size_t)blockIdx.y * 128;
    const int    bn = blockIdx.x * 96;

    float4 pa[4];
    float4 pb[3];

    auto ldg = [&](int kb) {
        #pragma unroll
        for (int i = 0; i < 4; ++i) {                 // 128x16 A chunk
            int idx = tid + i * 128;
            int r   = idx >> 2;
            int c4  = (idx & 3) * 4;
            pa[i] = *reinterpret_cast<const float4*>(A + (bm + r) * 192 + kb * 16 + c4);
        }
        #pragma unroll
        for (int i = 0; i < 3; ++i) {                 // 16x96 B chunk
            int idx = tid + i * 128;
            int r   = idx / 24;
            int c4  = (idx % 24) * 4;
            pb[i] = *reinterpret_cast<const float4*>(W + (size_t)(kb * 16 + r) * NT + bn + c4);
        }
    };
    auto sts = [&](int buf) {
        float* dA = sA + buf * SA_BUF;
        float* dB = sB + buf * SB_BUF;
        #pragma unroll
        for (int i = 0; i < 4; ++i) {
            int idx = tid + i * 128;
            int r   = idx >> 2;
            int c4  = (idx & 3) * 4;
            uint4 t;
            t.x = f2tf(pa[i].x); t.y = f2tf(pa[i].y);
            t.z = f2tf(pa[i].z); t.w = f2tf(pa[i].w);
            *reinterpret_cast<uint4*>(dA + r * SA_STR + c4) = t;
        }
        #pragma unroll
        for (int i = 0; i < 3; ++i) {
            int idx = tid + i * 128;
            int r   = idx / 24;
            int c4  = (idx % 24) * 4;
            uint4 t;
            t.x = f2tf(pb[i].x); t.y = f2tf(pb[i].y);
            t.z = f2tf(pb[i].z); t.w = f2tf(pb[i].w);
            *reinterpret_cast<uint4*>(dB + r * SB_STR + c4) = t;
        }
    };

    float acc[4][6][4];
    #pragma unroll
    for (int mt = 0; mt < 4; ++mt)
        #pragma unroll
        for (int nt = 0; nt < 6; ++nt)
            acc[mt][nt][0] = acc[mt][nt][1] = acc[mt][nt][2] = acc[mt][nt][3] = 0.f;

    ldg(0);
    sts(0);
    __syncthreads();

    #pragma unroll 2
    for (int kb = 0; kb < 12; ++kb) {
        if (kb < 11) ldg(kb + 1);
        const uint32_t* uA = reinterpret_cast<const uint32_t*>(sA + (kb & 1) * SA_BUF);
        const uint32_t* uB = reinterpret_cast<const uint32_t*>(sB + (kb & 1) * SB_BUF);
        #pragma unroll
        for (int ks = 0; ks < 2; ++ks) {
            const int k0 = ks * 8;
            uint32_t a[4][4];
            #pragma unroll
            for (int mt = 0; mt < 4; ++mt) {
                int rb = wm + mt * 16;
                a[mt][0] = uA[(rb + lr)     * SA_STR + k0 + lc];
                a[mt][1] = uA[(rb + lr + 8) * SA_STR + k0 + lc];
                a[mt][2] = uA[(rb + lr)     * SA_STR + k0 + lc + 4];
                a[mt][3] = uA[(rb + lr + 8) * SA_STR + k0 + lc + 4];
            }
            #pragma unroll
            for (int nt = 0; nt < 6; ++nt) {
                int n0 = wn + nt * 8;
                uint32_t b0 = uB[(k0 + lc)     * SB_STR + n0 + lr];
                uint32_t b1 = uB[(k0 + lc + 4) * SB_STR + n0 + lr];
                #pragma unroll
                for (int mt = 0; mt < 4; ++mt)
                    mma_tf32(acc[mt][nt], a[mt][0], a[mt][1], a[mt][2], a[mt][3], b0, b1);
            }
        }
        if (kb < 11) {
            sts((kb + 1) & 1);
            __syncthreads();
        }
    }

    // epilogue: + bias, direct store
    #pragma unroll
    for (int mt = 0; mt < 4; ++mt) {
        size_t r0 = bm + wm + mt * 16 + lr;
        size_t r1 = r0 + 8;
        #pragma unroll
        for (int nt = 0; nt < 6; ++nt) {
            int c = bn + wn + nt * 8 + lc * 2;
            float bb0 = bias[c];
            float bb1 = bias[c + 1];
            C[r0 * NT + c]     = acc[mt][nt][0] + bb0;
            C[r0 * NT + c + 1] = acc[mt][nt][1] + bb1;
            C[r1 * NT + c]     = acc[mt][nt][2] + bb0;
            C[r1 * NT + c + 1] = acc[mt][nt][3] + bb1;
        }
    }
}

extern "C" __global__ void __launch_bounds__(128, 3)
k1_qkv_gemm(const float* __restrict__ x,
            const float* __restrict__ qkv_w,
            const float* __restrict__ qkv_b)
{
    gemm_body<576>(x, qkv_w, qkv_b, g_qkv);
}

extern "C" __global__ void __launch_bounds__(128, 3)
k3_proj_gemm(const float* __restrict__ proj_w,
             const float* __restrict__ proj_b,
             float* __restrict__ out)
{
    gemm_body<192>(g_o, proj_w, proj_b, out);
}

// ---------------------------------------------------------------------------
// K2: attention. One CTA per (window, head). 128 threads (4 warps).
// smem: sQ/sK/sV 64x36 each + sS 64x68 = 45056 B.
// ---------------------------------------------------------------------------
extern "C" __global__ void __launch_bounds__(128)
k2_attention()
{
    extern __shared__ float sm[];
    float* sQ = sm;                //  64*36
    float* sK = sm + 64 * 36;
    float* sV = sm + 2 * 64 * 36;
    float* sS = sm + 3 * 64 * 36;  //  64*68

    const int win  = blockIdx.x;
    const int h    = blockIdx.y;
    const int tid  = threadIdx.x;
    const int w    = tid >> 5;
    const int lane = tid & 31;
    const int lr   = lane >> 2;
    const int lc   = lane & 3;
    const int m0   = w * 16;

    const size_t base = (size_t)win * NTOK * 576;
    const float* bh = g_bias + h * (NTOK * NTOK);

    for (int i = tid; i < 512; i += 128) {
        int r  = i >> 3;
        int c4 = (i & 7) * 4;
        float4 q = make_float4(0.f, 0.f, 0.f, 0.f);
        float4 k = q, v = q;
        if (r < NTOK) {
            const float* row = g_qkv + base + (size_t)r * 576 + h * HDIM + c4;
            q = *reinterpret_cast<const float4*>(row);
            k = *reinterpret_cast<const float4*>(row + 192);
            v = *reinterpret_cast<const float4*>(row + 384);
        }
        uint4 tq, tk, tv;
        tq.x = f2tf(q.x * QSCALE); tq.y = f2tf(q.y * QSCALE);
        tq.z = f2tf(q.z * QSCALE); tq.w = f2tf(q.w * QSCALE);
        tk.x = f2tf(k.x); tk.y = f2tf(k.y); tk.z = f2tf(k.z); tk.w = f2tf(k.w);
        tv.x = f2tf(v.x); tv.y = f2tf(v.y); tv.z = f2tf(v.z); tv.w = f2tf(v.w);
        *reinterpret_cast<uint4*>(sQ + r * 36 + c4) = tq;
        *reinterpret_cast<uint4*>(sK + r * 36 + c4) = tk;
        *reinterpret_cast<uint4*>(sV + r * 36 + c4) = tv;
    }
    __syncthreads();

    // --- S = Qs K^T + bias ---
    {
        const uint32_t* uQ = reinterpret_cast<const uint32_t*>(sQ);
        const uint32_t* uK = reinterpret_cast<const uint32_t*>(sK);
        float acc[8][4];
        #pragma unroll
        for (int nt = 0; nt < 8; ++nt)
            acc[nt][0] = acc[nt][1] = acc[nt][2] = acc[nt][3] = 0.f;
        #pragma unroll
        for (int kc = 0; kc < 4; ++kc) {
            uint32_t a0 = uQ[(m0 + lr)     * 36 + kc * 8 + lc];
            uint32_t a1 = uQ[(m0 + lr + 8) * 36 + kc * 8 + lc];
            uint32_t a2 = uQ[(m0 + lr)     * 36 + kc * 8 + lc + 4];
            uint32_t a3 = uQ[(m0 + lr + 8) * 36 + kc * 8 + lc + 4];
            #pragma unroll
            for (int nt = 0; nt < 8; ++nt) {
                uint32_t b0 = uK[(nt * 8 + lr) * 36 + kc * 8 + lc];
                uint32_t b1 = uK[(nt * 8 + lr) * 36 + kc * 8 + lc + 4];
                mma_tf32(acc[nt], a0, a1, a2, a3, b0, b1);
            }
        }
        #pragma unroll
        for (int nt = 0; nt < 8; ++nt) {
            #pragma unroll
            for (int half = 0; half < 2; ++half) {
                int rg = m0 + lr + half * 8;
                #pragma unroll
                for (int cc = 0; cc < 2; ++cc) {
                    int cgl = nt * 8 + lc * 2 + cc;
                    float s;
                    if (cgl < NTOK) {
                        s = acc[nt][half * 2 + cc];
                        if (rg < NTOK)
                            s += bh[rg * NTOK + cgl];
                    } else {
                        s = -1e30f;
                    }
                    sS[rg * 68 + cgl] = s;
                }
            }
        }
    }
    __syncthreads();

    // --- softmax: 2 threads per row ---
    {
        int row  = tid >> 1;
        int half = tid & 1;
        float* rp = sS + row * 68 + half * 32;
        float mx = -1e30f;
        #pragma unroll
        for (int j = 0; j < 32; ++j) mx = fmaxf(mx, rp[j]);
        mx = fmaxf(mx, __shfl_xor_sync(0xffffffffu, mx, 1));
        float sum = 0.f;
        #pragma unroll
        for (int j = 0; j < 32; ++j) {
            float e = __expf(rp[j] - mx);
            rp[j] = e;
            sum += e;
        }
        sum += __shfl_xor_sync(0xffffffffu, sum, 1);
        float inv = 1.f / sum;
        #pragma unroll
        for (int j = 0; j < 32; ++j)
            rp[j] = __uint_as_float(f2tf(rp[j] * inv));
    }
    __syncthreads();

    // --- O = P V ---
    {
        const uint32_t* uP = reinterpret_cast<const uint32_t*>(sS);
        const uint32_t* uV = reinterpret_cast<const uint32_t*>(sV);
        float acc[4][4];
        #pragma unroll
        for (int nt = 0; nt < 4; ++nt)
            acc[nt][0] = acc[nt][1] = acc[nt][2] = acc[nt][3] = 0.f;
        #pragma unroll
        for (int kc = 0; kc < 8; ++kc) {
            uint32_t a0 = uP[(m0 + lr)     * 68 + kc * 8 + lc];
            uint32_t a1 = uP[(m0 + lr + 8) * 68 + kc * 8 + lc];
            uint32_t a2 = uP[(m0 + lr)     * 68 + kc * 8 + lc + 4];
            uint32_t a3 = uP[(m0 + lr + 8) * 68 + kc * 8 + lc + 4];
            #pragma unroll
            for (int nt = 0; nt < 4; ++nt) {
                uint32_t b0 = uV[(kc * 8 + lc)     * 36 + nt * 8 + lr];
                uint32_t b1 = uV[(kc * 8 + lc + 4) * 36 + nt * 8 + lr];
                mma_tf32(acc[nt], a0, a1, a2, a3, b0, b1);
            }
        }
        int rg0 = m0 + lr;
        int rg1 = rg0 + 8;
        #pragma unroll
        for (int nt = 0; nt < 4; ++nt) {
            int cg = nt * 8 + lc * 2;
            if (rg0 < NTOK) {
                float* o = g_o + ((size_t)win * NTOK + rg0) * 192 + h * HDIM + cg;
                o[0] = acc[nt][0];
                o[1] = acc[nt][1];
            }
            if (rg1 < NTOK) {
                float* o = g_o + ((size_t)win * NTOK + rg1) * 192 + h * HDIM + cg;
                o[0] = acc[nt][2];
                o[1] = acc[nt][3];
            }
        }
    }
}

// ---------------------------------------------------------------------------

extern "C" void kernel_launch(void* const* d_in, const int* in_sizes, int n_in,
                              void* d_out, int out_size)
{
    const float* x          = (const float*)d_in[0];
    const float* qkv_w      = (const float*)d_in[1];
    const float* qkv_b      = (const float*)d_in[2];
    const float* proj_w     = (const float*)d_in[3];
    const float* proj_b     = (const float*)d_in[4];
    const float* bias_table = (const float*)d_in[5];
    const int*   rel_idx    = (const int*)d_in[6];
    float* out = (float*)d_out;

    const int M     = in_sizes[0] / DIM;   // 200704
    const int mblks = M / 128;             // 1568
    const int nwin  = M / NTOK;            // 4096

    const int attn_smem = (3 * 64 * 36 + 64 * 68) * 4;   // 45056

    k0_bias<<<NHEAD, 256>>>(bias_table, rel_idx);

    dim3 g1(6, mblks);                     // x = N-chunk (fast) -> A slab L2 reuse
    k1_qkv_gemm<<<g1, 128, GEMM_SMEM>>>(x, qkv_w, qkv_b);

    dim3 g2(nwin, NHEAD);
    k2_attention<<<g2, 128, attn_smem>>>();

    dim3 g3(2, mblks);
    k3_proj_gemm<<<g3, 128, GEMM_SMEM>>>(proj_w, proj_b, out);
}